// round 14
// baseline (speedup 1.0000x reference)
#include <cuda_runtime.h>
#include <cuda_bf16.h>
#include <stdint.h>
#include <math.h>

#define NROW 8192
#define THREADS 512
#define GRID 148
#define STRIDE_B 272u            // 136 bf16 per smem row (17x16B, conflict-free)
#define TILEB (128u * STRIDE_B)  // 34816
#define BUFOFF(b) ((uint32_t)(b) * 2u * TILEB)   // A at +0, B at +TILEB
#define YOFF   (4u * TILEB)                       // 139264: 2 bufs x 1024B
#define IP_OFF (YOFF + 2048u)                     // 141312: 3 x 10240B (128 rows x 20 words)
#define JP_OFF (IP_OFF + 30720u)                  // 172032: 3 x 18432B (128 cols x 36 words)
#define SMEM_TOTAL (JP_OFF + 55296u)              // 227328 <= 232448

#define PLANE 524288             // 64*64*128 floats per stat plane

__device__ __nv_bfloat16 g_xb[NROW * 128];
// P[s][a][b][r]: s=0 denom, 1 S, 2 m. Every slot written exactly once per launch.
__device__ float g_P[3 * PLANE];
__device__ float g_part[64];
__device__ int   g_ctr;              // zero-init; self-resets each launch
__device__ int   g_bar_cnt;          // grid-barrier counter; self-resets
__device__ volatile int g_bar_gen;   // grid-barrier generation; monotonic across replays

// ---------------- PTX helpers ----------------
__device__ __forceinline__ uint32_t smem_u32(const void* p) {
    uint32_t a;
    asm("{ .reg .u64 t; cvta.to.shared.u64 t, %1; cvt.u32.u64 %0, t; }" : "=r"(a) : "l"(p));
    return a;
}
#define LDSM4(r, a) \
    asm volatile("ldmatrix.sync.aligned.m8n8.x4.shared.b16 {%0,%1,%2,%3}, [%4];" \
        : "=r"((r)[0]), "=r"((r)[1]), "=r"((r)[2]), "=r"((r)[3]) : "r"(a))
#define MMA16816(c, a, b0v, b1v) \
    asm volatile("mma.sync.aligned.m16n8k16.row.col.f32.bf16.bf16.f32 " \
        "{%0,%1,%2,%3}, {%4,%5,%6,%7}, {%8,%9}, {%0,%1,%2,%3};" \
        : "+f"((c)[0]), "+f"((c)[1]), "+f"((c)[2]), "+f"((c)[3]) \
        : "r"((a)[0]), "r"((a)[1]), "r"((a)[2]), "r"((a)[3]), "r"(b0v), "r"(b1v))
#define CP_ASYNC16(dst, src) \
    asm volatile("cp.async.cg.shared.global [%0], [%1], 16;" :: "r"(dst), "l"(src))
#define CP_ASYNC4(dst, src) \
    asm volatile("cp.async.ca.shared.global [%0], [%1], 4;" :: "r"(dst), "l"(src))
#define CP_COMMIT() asm volatile("cp.async.commit_group;" ::: "memory")
#define CP_WAIT1()  asm volatile("cp.async.wait_group 1;" ::: "memory")
#define CP_WAIT0()  asm volatile("cp.async.wait_group 0;" ::: "memory")

// All 148 CTAs are co-resident (1 CTA/SM, 148 <= 152 SMs) -> spin barrier is safe.
__device__ __forceinline__ void grid_sync() {
    __syncthreads();
    if (threadIdx.x == 0) {
        __threadfence();                       // publish this CTA's global writes
        int gen = g_bar_gen;
        if (atomicAdd(&g_bar_cnt, 1) == GRID - 1) {
            g_bar_cnt = 0;
            __threadfence();
            g_bar_gen = gen + 1;
        } else {
            while (g_bar_gen == gen) { }
        }
    }
    __syncthreads();
}

// ---------------- off-diagonal index u in [0,2016) -> (bi, bj), bi < bj ----------------
__device__ __forceinline__ void offdiag(int u, int& bi, int& bj) {
    int k = (int)((1.0f + __fsqrt_rn(1.0f + 8.0f * (float)u)) * 0.5f);
    while (k * (k - 1) / 2 > u) --k;
    while ((k + 1) * k / 2 <= u) ++k;
    bi = 63 - k;
    bj = 63 - (u - k * (k - 1) / 2);
}

// Balanced schedule: CTAs 0-7 run 15 tiles (8 diagonal + 7 off-diag);
// CTAs 8-147 run 14 off-diag tiles.
__device__ __forceinline__ void sched(int b, int it, int& bi, int& bj) {
    if (b < 8) {
        if (it < 8) { bi = bj = b * 8 + it; return; }
        offdiag(b * 7 + (it - 8), bi, bj);
    } else {
        offdiag(56 + (b - 8) * 14 + it, bi, bj);
    }
}

__device__ __forceinline__ void prefetch_tile(uint32_t sbase, int buf,
                                              int bi, int bj, const uint4* xg,
                                              const int* y, int tid) {
    uint32_t dst = sbase + BUFOFF(buf);
    const int arow = bi * 128, brow = bj * 128;
#pragma unroll
    for (int q = 0; q < 4; ++q) {
        int idx = tid + q * THREADS;
        int row = idx >> 4, c16 = idx & 15;
        CP_ASYNC16(dst + row * STRIDE_B + c16 * 16, (const void*)(xg + (arow + row) * 16 + c16));
    }
#pragma unroll
    for (int q = 0; q < 4; ++q) {
        int idx = tid + q * THREADS;
        int row = idx >> 4, c16 = idx & 15;
        CP_ASYNC16(dst + TILEB + row * STRIDE_B + c16 * 16, (const void*)(xg + (brow + row) * 16 + c16));
    }
    if (tid < 128)
        CP_ASYNC4(sbase + YOFF + (uint32_t)buf * 1024u + tid * 4, (const void*)(y + arow + tid));
    else if (tid < 256)
        CP_ASYNC4(sbase + YOFF + (uint32_t)buf * 1024u + 512u + (tid - 128) * 4,
                  (const void*)(y + brow + (tid - 128)));
    CP_COMMIT();
}

// ---------------- Fused kernel: norm -> barrier -> symmetric Gram -> barrier -> finish --
__global__ void __launch_bounds__(THREADS, 1) scl_fused_kernel(
        const float* __restrict__ x, const int* __restrict__ y,
        float* __restrict__ out) {
    extern __shared__ char smem[];
    const uint32_t sbase = smem_u32(smem);
    const int tid = threadIdx.x, wid = tid >> 5, lane = tid & 31;
    const int wi = wid & 3, wj = wid >> 2;
    const int grp = lane >> 2;
    const int b = blockIdx.x;
    const int niter = (b < 8) ? 15 : 14;

    // ===== Phase 0: normalize + bf16 convert (56 rows per CTA) =====
    {
        const int base = b * 56;
        const int lim = (base + 56 < NROW) ? base + 56 : NROW;
#pragma unroll
        for (int itn = 0; itn < 2; ++itn) {
            int r0 = base + (itn * 16 + wid) * 2;
            if (r0 < lim) {
                float4 v0 = reinterpret_cast<const float4*>(x)[r0 * 32 + lane];
                float4 v1 = reinterpret_cast<const float4*>(x)[(r0 + 1) * 32 + lane];
                float s0 = v0.x * v0.x + v0.y * v0.y + v0.z * v0.z + v0.w * v0.w;
                float s1 = v1.x * v1.x + v1.y * v1.y + v1.z * v1.z + v1.w * v1.w;
#pragma unroll
                for (int o = 16; o; o >>= 1) {
                    s0 += __shfl_xor_sync(0xffffffffu, s0, o);
                    s1 += __shfl_xor_sync(0xffffffffu, s1, o);
                }
                float i0 = 1.0f / fmaxf(sqrtf(s0), 1e-12f);
                float i1 = 1.0f / fmaxf(sqrtf(s1), 1e-12f);
                v0.x *= i0; v0.y *= i0; v0.z *= i0; v0.w *= i0;
                v1.x *= i1; v1.y *= i1; v1.z *= i1; v1.w *= i1;
                uint32_t a0 = ((uint32_t)__bfloat16_as_ushort(__float2bfloat16(v0.y)) << 16)
                            |  (uint32_t)__bfloat16_as_ushort(__float2bfloat16(v0.x));
                uint32_t a1 = ((uint32_t)__bfloat16_as_ushort(__float2bfloat16(v0.w)) << 16)
                            |  (uint32_t)__bfloat16_as_ushort(__float2bfloat16(v0.z));
                uint32_t c0 = ((uint32_t)__bfloat16_as_ushort(__float2bfloat16(v1.y)) << 16)
                            |  (uint32_t)__bfloat16_as_ushort(__float2bfloat16(v1.x));
                uint32_t c1 = ((uint32_t)__bfloat16_as_ushort(__float2bfloat16(v1.w)) << 16)
                            |  (uint32_t)__bfloat16_as_ushort(__float2bfloat16(v1.z));
                reinterpret_cast<uint2*>(g_xb)[r0 * 32 + lane] = make_uint2(a0, a1);
                reinterpret_cast<uint2*>(g_xb)[(r0 + 1) * 32 + lane] = make_uint2(c0, c1);
            }
        }
    }
    grid_sync();   // g_xb fully published

    // ===== Phase 1: symmetric Gram + dual-orientation stats =====
    const uint4* xg = reinterpret_cast<const uint4*>(g_xb);
    float* ipE = reinterpret_cast<float*>(smem + IP_OFF);          // 128 x 20 words
    float* ipS = ipE + 2560; float* ipM = ipE + 5120;
    float* jpE = reinterpret_cast<float*>(smem + JP_OFF);          // 128 x 36 words
    float* jpS = jpE + 4608; float* jpM = jpE + 9216;

    uint32_t aRel[2], bRel[2];
#pragma unroll
    for (int mi = 0; mi < 2; ++mi)
        aRel[mi] = (uint32_t)((wi * 32 + mi * 16 + (lane & 15)) * STRIDE_B + (lane >> 4) * 16);
#pragma unroll
    for (int nb = 0; nb < 2; ++nb)
        bRel[nb] = (uint32_t)((wj * 32 + nb * 16 + (lane & 7) + (lane >> 4) * 8) * STRIDE_B
                   + ((lane >> 3) & 1) * 16);

    {
        int bi0, bj0; sched(b, 0, bi0, bj0);
        prefetch_tile(sbase, 0, bi0, bj0, xg, y, tid);
    }

    for (int it = 0; it < niter; ++it) {
        int bi, bj; sched(b, it, bi, bj);
        if (it + 1 < niter) {
            int nbi, nbj; sched(b, it + 1, nbi, nbj);
            prefetch_tile(sbase, (it + 1) & 1, nbi, nbj, xg, y, tid);
            CP_WAIT1();
        } else {
            CP_WAIT0();
        }
        __syncthreads();

        const uint32_t abase = sbase + BUFOFF(it & 1);
        const uint32_t bbase = abase + TILEB;
        const int* yI = reinterpret_cast<const int*>(smem + YOFF + (it & 1) * 1024);
        const int* yJ = yI + 128;
        const bool isDiag = (bi == bj);

        float acc[2][4][4];
#pragma unroll
        for (int mi = 0; mi < 2; ++mi)
#pragma unroll
            for (int p = 0; p < 4; ++p)
#pragma unroll
                for (int c = 0; c < 4; ++c) acc[mi][p][c] = 0.f;

#pragma unroll
        for (int kk = 0; kk < 8; ++kk) {
            uint32_t a0[4], a1[4], b0[4], b1[4];
            LDSM4(a0, abase + aRel[0] + kk * 32);
            LDSM4(a1, abase + aRel[1] + kk * 32);
            LDSM4(b0, bbase + bRel[0] + kk * 32);
            LDSM4(b1, bbase + bRel[1] + kk * 32);
            MMA16816(acc[0][0], a0, b0[0], b0[1]);
            MMA16816(acc[0][1], a0, b0[2], b0[3]);
            MMA16816(acc[0][2], a0, b1[0], b1[1]);
            MMA16816(acc[0][3], a0, b1[2], b1[3]);
            MMA16816(acc[1][0], a1, b0[0], b0[1]);
            MMA16816(acc[1][1], a1, b0[2], b0[3]);
            MMA16816(acc[1][2], a1, b1[0], b1[1]);
            MMA16816(acc[1][3], a1, b1[2], b1[3]);
        }

        int yiv[2][2];
#pragma unroll
        for (int mi = 0; mi < 2; ++mi)
#pragma unroll
            for (int rh = 0; rh < 2; ++rh)
                yiv[mi][rh] = yI[wi * 32 + mi * 16 + rh * 8 + grp];

        float dnm[2][2] = {{0.f,0.f},{0.f,0.f}};
        float Ss [2][2] = {{0.f,0.f},{0.f,0.f}};
        float mm [2][2] = {{0.f,0.f},{0.f,0.f}};

        if (!isDiag) {
#pragma unroll
            for (int p = 0; p < 4; ++p) {
                const int jl = wj * 32 + (p >> 1) * 16 + (p & 1) * 8 + 2 * (lane & 3);
                const int yj0 = yJ[jl], yj1 = yJ[jl + 1];
                float cE0=0.f,cE1=0.f,cS0=0.f,cS1=0.f,cM0=0.f,cM1=0.f;
#pragma unroll
                for (int mi = 0; mi < 2; ++mi)
#pragma unroll
                    for (int rh = 0; rh < 2; ++rh) {
                        const float d0 = acc[mi][p][rh * 2 + 0];
                        const float d1 = acc[mi][p][rh * 2 + 1];
                        const float e0 = __expf(10.0f * d0);
                        const float e1 = __expf(10.0f * d1);
                        const int yi = yiv[mi][rh];
                        const float m0 = (yj0 == yi) ? 1.0f : 0.0f;
                        const float m1 = (yj1 == yi) ? 1.0f : 0.0f;
                        dnm[mi][rh] += e0 + e1;
                        Ss[mi][rh]  = fmaf(d0, m0, fmaf(d1, m1, Ss[mi][rh]));
                        mm[mi][rh] += m0 + m1;
                        cE0 += e0; cE1 += e1;
                        cS0 = fmaf(d0, m0, cS0); cS1 = fmaf(d1, m1, cS1);
                        cM0 += m0; cM1 += m1;
                    }
                const int s0 = jl * 36 + wi * 8 + grp, s1 = s0 + 36;
                jpE[s0] = cE0; jpE[s1] = cE1;
                jpS[s0] = cS0; jpS[s1] = cS1;
                jpM[s0] = cM0; jpM[s1] = cM1;
            }
        } else {
#pragma unroll
            for (int p = 0; p < 4; ++p) {
                const int jl = wj * 32 + (p >> 1) * 16 + (p & 1) * 8 + 2 * (lane & 3);
                const int yj0 = yJ[jl], yj1 = yJ[jl + 1];
#pragma unroll
                for (int mi = 0; mi < 2; ++mi)
#pragma unroll
                    for (int rh = 0; rh < 2; ++rh) {
                        const float d0 = acc[mi][p][rh * 2 + 0];
                        const float d1 = acc[mi][p][rh * 2 + 1];
                        float e0 = __expf(10.0f * d0);
                        float e1 = __expf(10.0f * d1);
                        const int yi = yiv[mi][rh];
                        const int rowloc = wi * 32 + mi * 16 + rh * 8 + grp;
                        float m0 = (yj0 == yi) ? 1.0f : 0.0f;
                        float m1 = (yj1 == yi) ? 1.0f : 0.0f;
                        if (jl == rowloc)     { e0 = 0.0f; m0 = 0.0f; }
                        if (jl + 1 == rowloc) { e1 = 0.0f; m1 = 0.0f; }
                        dnm[mi][rh] += e0 + e1;
                        Ss[mi][rh]  = fmaf(d0, m0, fmaf(d1, m1, Ss[mi][rh]));
                        mm[mi][rh] += m0 + m1;
                    }
            }
        }

#pragma unroll
        for (int mi = 0; mi < 2; ++mi)
#pragma unroll
            for (int rh = 0; rh < 2; ++rh) {
                const int row = wi * 32 + mi * 16 + rh * 8 + grp;
                const int sl = row * 20 + wj * 4 + (lane & 3);
                ipE[sl] = dnm[mi][rh]; ipS[sl] = Ss[mi][rh]; ipM[sl] = mm[mi][rh];
            }
        __syncthreads();

        const int ntask = isDiag ? 384 : 768;
        for (int task = tid; task < ntask; task += THREADS) {
            if (task < 384) {
                const int stat = task >> 7, row = task & 127;
                const float* src = ipE + stat * 2560 + row * 20;
                float s = 0.f;
#pragma unroll
                for (int q = 0; q < 4; ++q) {
                    float4 v = *reinterpret_cast<const float4*>(src + q * 4);
                    s += (v.x + v.y) + (v.z + v.w);
                }
                g_P[stat * PLANE + bi * 8192 + bj * 128 + row] = s;
            } else {
                const int tt = task - 384;
                const int stat = tt >> 7, col = tt & 127;
                const float* src = jpE + stat * 4608 + col * 36;
                float s = 0.f;
#pragma unroll
                for (int q = 0; q < 8; ++q) {
                    float4 v = *reinterpret_cast<const float4*>(src + q * 4);
                    s += (v.x + v.y) + (v.z + v.w);
                }
                g_P[stat * PLANE + bj * 8192 + bi * 128 + col] = s;
            }
        }
    }

    // ===== Phase 2: finish (g_P fully published by the barrier) =====
    grid_sync();
    if (b < 64) {
        float v = 0.f;
        if (tid < 128) {
            float D = 0.f, S = 0.f, M = 0.f;
            const int base = b * 8192 + tid;
#pragma unroll 8
            for (int c = 0; c < 64; ++c) {
                D += g_P[base + c * 128];
                S += g_P[PLANE + base + c * 128];
                M += g_P[2 * PLANE + base + c * 128];
            }
            v = (M > 0.5f) ? (logf(D) - 10.0f * S / M) : 0.0f;
#pragma unroll
            for (int o = 16; o; o >>= 1) v += __shfl_xor_sync(0xffffffffu, v, o);
        }
        float* red = reinterpret_cast<float*>(smem + IP_OFF);
        if (tid < 128 && (lane == 0)) red[wid] = v;
        __syncthreads();
        if (tid == 0) {
            g_part[b] = (red[0] + red[1]) + (red[2] + red[3]);
            __threadfence();
            if (atomicAdd(&g_ctr, 1) == 63) {
                float s = 0.f;
#pragma unroll 8
                for (int i = 0; i < 64; ++i) s += g_part[i];
                out[0] = s;
                g_ctr = 0;     // reset for graph replay
            }
        }
    }
}

// ---------------------------------------------------------------------------
extern "C" void kernel_launch(void* const* d_in, const int* in_sizes, int n_in,
                              void* d_out, int out_size) {
    (void)in_sizes; (void)n_in; (void)out_size;
    const float* x = (const float*)d_in[0];
    const int*   y = (const int*)d_in[1];
    float* out = (float*)d_out;

    cudaFuncSetAttribute(scl_fused_kernel,
                         cudaFuncAttributeMaxDynamicSharedMemorySize, SMEM_TOTAL);

    scl_fused_kernel<<<GRID, THREADS, SMEM_TOTAL>>>(x, y, out);
}

// round 15
// speedup vs baseline: 1.0244x; 1.0244x over previous
#include <cuda_runtime.h>
#include <cuda_bf16.h>
#include <stdint.h>
#include <math.h>

#define NROW 8192
#define THREADS 1024
#define GRID 148
#define STRIDE_B 272u            // 136 bf16 per smem row (17x16B, conflict-free)
#define TILEB (128u * STRIDE_B)  // 34816
#define BUFOFF(b) ((uint32_t)(b) * 2u * TILEB)   // A at +0, B at +TILEB
#define YOFF   (4u * TILEB)                       // 139264: 2 bufs x 1024B
#define IP_OFF (YOFF + 2048u)                     // 141312: 3 x 10240B (128 rows x 20 words)
#define JP_OFF (IP_OFF + 30720u)                  // 172032: 3 x 10240B (128 cols x 20 words)
#define SMEM_TOTAL (JP_OFF + 30720u)              // 202752 <= 232448

#define PLANE 524288             // 64*64*128 floats per stat plane

__device__ __nv_bfloat16 g_xb[NROW * 128];
// P[s][a][b][r]: s=0 denom, 1 S, 2 m. Every slot written exactly once per launch.
__device__ float g_P[3 * PLANE];
__device__ float g_part[64];
__device__ int   g_ctr;          // zero-init; self-resets each launch

// ---------------- PTX helpers ----------------
__device__ __forceinline__ uint32_t smem_u32(const void* p) {
    uint32_t a;
    asm("{ .reg .u64 t; cvta.to.shared.u64 t, %1; cvt.u32.u64 %0, t; }" : "=r"(a) : "l"(p));
    return a;
}
#define LDSM4(r, a) \
    asm volatile("ldmatrix.sync.aligned.m8n8.x4.shared.b16 {%0,%1,%2,%3}, [%4];" \
        : "=r"((r)[0]), "=r"((r)[1]), "=r"((r)[2]), "=r"((r)[3]) : "r"(a))
#define MMA16816(c, a, b0v, b1v) \
    asm volatile("mma.sync.aligned.m16n8k16.row.col.f32.bf16.bf16.f32 " \
        "{%0,%1,%2,%3}, {%4,%5,%6,%7}, {%8,%9}, {%0,%1,%2,%3};" \
        : "+f"((c)[0]), "+f"((c)[1]), "+f"((c)[2]), "+f"((c)[3]) \
        : "r"((a)[0]), "r"((a)[1]), "r"((a)[2]), "r"((a)[3]), "r"(b0v), "r"(b1v))
#define CP_ASYNC16(dst, src) \
    asm volatile("cp.async.cg.shared.global [%0], [%1], 16;" :: "r"(dst), "l"(src))
#define CP_ASYNC4(dst, src) \
    asm volatile("cp.async.ca.shared.global [%0], [%1], 4;" :: "r"(dst), "l"(src))
#define CP_COMMIT() asm volatile("cp.async.commit_group;" ::: "memory")
#define CP_WAIT1()  asm volatile("cp.async.wait_group 1;" ::: "memory")
#define CP_WAIT0()  asm volatile("cp.async.wait_group 0;" ::: "memory")

// ---------------- Kernel 1: normalize + bf16 convert (2 rows/warp) ----------------
__global__ void __launch_bounds__(256) norm_kernel(const float* __restrict__ x) {
    int warp = threadIdx.x >> 5, lane = threadIdx.x & 31;
    int row0 = (blockIdx.x * 8 + warp) * 2;
    float4 v0 = reinterpret_cast<const float4*>(x)[row0 * 32 + lane];
    float4 v1 = reinterpret_cast<const float4*>(x)[(row0 + 1) * 32 + lane];
    float s0 = v0.x * v0.x + v0.y * v0.y + v0.z * v0.z + v0.w * v0.w;
    float s1 = v1.x * v1.x + v1.y * v1.y + v1.z * v1.z + v1.w * v1.w;
#pragma unroll
    for (int o = 16; o; o >>= 1) {
        s0 += __shfl_xor_sync(0xffffffffu, s0, o);
        s1 += __shfl_xor_sync(0xffffffffu, s1, o);
    }
    float i0 = 1.0f / fmaxf(sqrtf(s0), 1e-12f);
    float i1 = 1.0f / fmaxf(sqrtf(s1), 1e-12f);
    v0.x *= i0; v0.y *= i0; v0.z *= i0; v0.w *= i0;
    v1.x *= i1; v1.y *= i1; v1.z *= i1; v1.w *= i1;
    uint32_t a0 = ((uint32_t)__bfloat16_as_ushort(__float2bfloat16(v0.y)) << 16)
                |  (uint32_t)__bfloat16_as_ushort(__float2bfloat16(v0.x));
    uint32_t a1 = ((uint32_t)__bfloat16_as_ushort(__float2bfloat16(v0.w)) << 16)
                |  (uint32_t)__bfloat16_as_ushort(__float2bfloat16(v0.z));
    uint32_t b0 = ((uint32_t)__bfloat16_as_ushort(__float2bfloat16(v1.y)) << 16)
                |  (uint32_t)__bfloat16_as_ushort(__float2bfloat16(v1.x));
    uint32_t b1 = ((uint32_t)__bfloat16_as_ushort(__float2bfloat16(v1.w)) << 16)
                |  (uint32_t)__bfloat16_as_ushort(__float2bfloat16(v1.z));
    reinterpret_cast<uint2*>(g_xb)[row0 * 32 + lane] = make_uint2(a0, a1);
    reinterpret_cast<uint2*>(g_xb)[(row0 + 1) * 32 + lane] = make_uint2(b0, b1);
}

// ---------------- off-diagonal index u in [0,2016) -> (bi, bj), bi < bj ----------------
__device__ __forceinline__ void offdiag(int u, int& bi, int& bj) {
    int k = (int)((1.0f + __fsqrt_rn(1.0f + 8.0f * (float)u)) * 0.5f);
    while (k * (k - 1) / 2 > u) --k;
    while ((k + 1) * k / 2 <= u) ++k;
    bi = 63 - k;
    bj = 63 - (u - k * (k - 1) / 2);
}

// Balanced schedule: CTAs 0-7 run 15 tiles (8 diagonal + 7 off-diag);
// CTAs 8-147 run 14 off-diag tiles.
__device__ __forceinline__ void sched(int b, int it, int& bi, int& bj) {
    if (b < 8) {
        if (it < 8) { bi = bj = b * 8 + it; return; }
        offdiag(b * 7 + (it - 8), bi, bj);
    } else {
        offdiag(56 + (b - 8) * 14 + it, bi, bj);
    }
}

__device__ __forceinline__ void prefetch_tile(uint32_t sbase, int buf,
                                              int bi, int bj, const uint4* xg,
                                              const int* y, int tid) {
    uint32_t dst = sbase + BUFOFF(buf);
    const int arow = bi * 128, brow = bj * 128;
#pragma unroll
    for (int q = 0; q < 2; ++q) {
        int idx = tid + q * THREADS;
        int row = idx >> 4, c16 = idx & 15;
        CP_ASYNC16(dst + row * STRIDE_B + c16 * 16, (const void*)(xg + (arow + row) * 16 + c16));
    }
#pragma unroll
    for (int q = 0; q < 2; ++q) {
        int idx = tid + q * THREADS;
        int row = idx >> 4, c16 = idx & 15;
        CP_ASYNC16(dst + TILEB + row * STRIDE_B + c16 * 16, (const void*)(xg + (brow + row) * 16 + c16));
    }
    if (tid < 128)
        CP_ASYNC4(sbase + YOFF + (uint32_t)buf * 1024u + tid * 4, (const void*)(y + arow + tid));
    else if (tid < 256)
        CP_ASYNC4(sbase + YOFF + (uint32_t)buf * 1024u + 512u + (tid - 128) * 4,
                  (const void*)(y + brow + (tid - 128)));
    CP_COMMIT();
}

// ---------------- Kernel 2: symmetric Gram, 32 warps (8x4 grid) ----------------
__global__ void __launch_bounds__(THREADS, 1) scl_mma_kernel(const int* __restrict__ y) {
    extern __shared__ char smem[];
    const uint32_t sbase = smem_u32(smem);
    const int tid = threadIdx.x, wid = tid >> 5, lane = tid & 31;
    const int wi = wid & 7, wj = wid >> 3;       // 8 row-strips x 4 col-strips
    const int grp = lane >> 2;
    const int b = blockIdx.x;
    const int niter = (b < 8) ? 15 : 14;

    const uint4* xg = reinterpret_cast<const uint4*>(g_xb);
    float* ipE = reinterpret_cast<float*>(smem + IP_OFF);          // 128 x 20 words
    float* ipS = ipE + 2560; float* ipM = ipE + 5120;
    float* jpE = reinterpret_cast<float*>(smem + JP_OFF);          // 128 x 20 words
    float* jpS = jpE + 2560; float* jpM = jpE + 5120;

    // relative ldmatrix offsets: A = 16 rows (one x4), B = 2 x4 for 32 cols
    const uint32_t aRel = (uint32_t)((wi * 16 + (lane & 15)) * STRIDE_B + (lane >> 4) * 16);
    uint32_t bRel[2];
#pragma unroll
    for (int nb = 0; nb < 2; ++nb)
        bRel[nb] = (uint32_t)((wj * 32 + nb * 16 + (lane & 7) + (lane >> 4) * 8) * STRIDE_B
                   + ((lane >> 3) & 1) * 16);

    {
        int bi0, bj0; sched(b, 0, bi0, bj0);
        prefetch_tile(sbase, 0, bi0, bj0, xg, y, tid);
    }

    for (int it = 0; it < niter; ++it) {
        int bi, bj; sched(b, it, bi, bj);
        if (it + 1 < niter) {
            int nbi, nbj; sched(b, it + 1, nbi, nbj);
            prefetch_tile(sbase, (it + 1) & 1, nbi, nbj, xg, y, tid);
            CP_WAIT1();
        } else {
            CP_WAIT0();
        }
        __syncthreads();

        const uint32_t abase = sbase + BUFOFF(it & 1);
        const uint32_t bbase = abase + TILEB;
        const int* yI = reinterpret_cast<const int*>(smem + YOFF + (it & 1) * 1024);
        const int* yJ = yI + 128;
        const bool isDiag = (bi == bj);

        float acc[4][4];
#pragma unroll
        for (int p = 0; p < 4; ++p)
#pragma unroll
            for (int c = 0; c < 4; ++c) acc[p][c] = 0.f;

#pragma unroll
        for (int kk = 0; kk < 8; ++kk) {
            uint32_t a0[4], b0[4], b1[4];
            LDSM4(a0, abase + aRel + kk * 32);
            LDSM4(b0, bbase + bRel[0] + kk * 32);
            LDSM4(b1, bbase + bRel[1] + kk * 32);
            MMA16816(acc[0], a0, b0[0], b0[1]);
            MMA16816(acc[1], a0, b0[2], b0[3]);
            MMA16816(acc[2], a0, b1[0], b1[1]);
            MMA16816(acc[3], a0, b1[2], b1[3]);
        }

        int yiv[2];
#pragma unroll
        for (int rh = 0; rh < 2; ++rh)
            yiv[rh] = yI[wi * 16 + rh * 8 + grp];

        float dnm[2] = {0.f, 0.f}, Ss[2] = {0.f, 0.f}, mm[2] = {0.f, 0.f};

        if (!isDiag) {
#pragma unroll
            for (int p = 0; p < 4; ++p) {
                const int jl = wj * 32 + (p >> 1) * 16 + (p & 1) * 8 + 2 * (lane & 3);
                const int yj0 = yJ[jl], yj1 = yJ[jl + 1];
                float cE0=0.f,cE1=0.f,cS0=0.f,cS1=0.f,cM0=0.f,cM1=0.f;
#pragma unroll
                for (int rh = 0; rh < 2; ++rh) {
                    const float d0 = acc[p][rh * 2 + 0];
                    const float d1 = acc[p][rh * 2 + 1];
                    const float e0 = __expf(10.0f * d0);
                    const float e1 = __expf(10.0f * d1);
                    const int yi = yiv[rh];
                    const float m0 = (yj0 == yi) ? 1.0f : 0.0f;
                    const float m1 = (yj1 == yi) ? 1.0f : 0.0f;
                    dnm[rh] += e0 + e1;
                    Ss[rh]  = fmaf(d0, m0, fmaf(d1, m1, Ss[rh]));
                    mm[rh] += m0 + m1;
                    cE0 += e0; cE1 += e1;
                    cS0 = fmaf(d0, m0, cS0); cS1 = fmaf(d1, m1, cS1);
                    cM0 += m0; cM1 += m1;
                }
                // reduce across grp (rows) within warp: offsets 4, 8, 16
#pragma unroll
                for (int o = 4; o <= 16; o <<= 1) {
                    cE0 += __shfl_xor_sync(0xffffffffu, cE0, o);
                    cE1 += __shfl_xor_sync(0xffffffffu, cE1, o);
                    cS0 += __shfl_xor_sync(0xffffffffu, cS0, o);
                    cS1 += __shfl_xor_sync(0xffffffffu, cS1, o);
                    cM0 += __shfl_xor_sync(0xffffffffu, cM0, o);
                    cM1 += __shfl_xor_sync(0xffffffffu, cM1, o);
                }
                if (grp == 0) {
                    const int s0 = jl * 20 + wi, s1 = s0 + 20;
                    jpE[s0] = cE0; jpE[s1] = cE1;
                    jpS[s0] = cS0; jpS[s1] = cS1;
                    jpM[s0] = cM0; jpM[s1] = cM1;
                }
            }
        } else {
#pragma unroll
            for (int p = 0; p < 4; ++p) {
                const int jl = wj * 32 + (p >> 1) * 16 + (p & 1) * 8 + 2 * (lane & 3);
                const int yj0 = yJ[jl], yj1 = yJ[jl + 1];
#pragma unroll
                for (int rh = 0; rh < 2; ++rh) {
                    const float d0 = acc[p][rh * 2 + 0];
                    const float d1 = acc[p][rh * 2 + 1];
                    float e0 = __expf(10.0f * d0);
                    float e1 = __expf(10.0f * d1);
                    const int yi = yiv[rh];
                    const int rowloc = wi * 16 + rh * 8 + grp;
                    float m0 = (yj0 == yi) ? 1.0f : 0.0f;
                    float m1 = (yj1 == yi) ? 1.0f : 0.0f;
                    if (jl == rowloc)     { e0 = 0.0f; m0 = 0.0f; }
                    if (jl + 1 == rowloc) { e1 = 0.0f; m1 = 0.0f; }
                    dnm[rh] += e0 + e1;
                    Ss[rh]  = fmaf(d0, m0, fmaf(d1, m1, Ss[rh]));
                    mm[rh] += m0 + m1;
                }
            }
        }

        // i-orientation per-thread partials: slot = row*20 + wj*4 + (lane&3)
#pragma unroll
        for (int rh = 0; rh < 2; ++rh) {
            const int row = wi * 16 + rh * 8 + grp;
            const int sl = row * 20 + wj * 4 + (lane & 3);
            ipE[sl] = dnm[rh]; ipS[sl] = Ss[rh]; ipM[sl] = mm[rh];
        }
        __syncthreads();

        // store phase: sum partials, write g_P (each slot exactly once per launch)
        const int ntask = isDiag ? 384 : 768;
        if (tid < ntask) {
            const int task = tid;
            if (task < 384) {
                const int stat = task >> 7, row = task & 127;
                const float* src = ipE + stat * 2560 + row * 20;
                float s = 0.f;
#pragma unroll
                for (int q = 0; q < 4; ++q) {
                    float4 v = *reinterpret_cast<const float4*>(src + q * 4);
                    s += (v.x + v.y) + (v.z + v.w);
                }
                g_P[stat * PLANE + bi * 8192 + bj * 128 + row] = s;
            } else {
                const int tt = task - 384;
                const int stat = tt >> 7, col = tt & 127;
                const float* src = jpE + stat * 2560 + col * 20;
                float s = 0.f;
#pragma unroll
                for (int q = 0; q < 2; ++q) {
                    float4 v = *reinterpret_cast<const float4*>(src + q * 4);
                    s += (v.x + v.y) + (v.z + v.w);
                }
                g_P[stat * PLANE + bj * 8192 + bi * 128 + col] = s;
            }
        }
        // loop-top CP_WAIT + __syncthreads orders partial-zone reuse next iteration
    }
}

// ---------------- Kernel 3: fused per-row loss + global sum ----------------
__global__ void __launch_bounds__(128) finish_kernel(float* __restrict__ out) {
    const int A = blockIdx.x, r = threadIdx.x;
    float D = 0.f, S = 0.f, M = 0.f;
    const int base = A * 8192 + r;
#pragma unroll 8
    for (int c = 0; c < 64; ++c) {
        D += g_P[base + c * 128];
        S += g_P[PLANE + base + c * 128];
        M += g_P[2 * PLANE + base + c * 128];
    }
    float v = (M > 0.5f) ? (logf(D) - 10.0f * S / M) : 0.0f;
    __shared__ float red[4];
#pragma unroll
    for (int o = 16; o; o >>= 1) v += __shfl_xor_sync(0xffffffffu, v, o);
    if ((r & 31) == 0) red[r >> 5] = v;
    __syncthreads();
    if (r == 0) {
        g_part[A] = (red[0] + red[1]) + (red[2] + red[3]);
        __threadfence();
        if (atomicAdd(&g_ctr, 1) == 63) {
            float s = 0.f;
#pragma unroll 8
            for (int i = 0; i < 64; ++i) s += g_part[i];
            out[0] = s;
            g_ctr = 0;     // reset for graph replay
        }
    }
}

// ---------------------------------------------------------------------------
extern "C" void kernel_launch(void* const* d_in, const int* in_sizes, int n_in,
                              void* d_out, int out_size) {
    (void)in_sizes; (void)n_in; (void)out_size;
    const float* x = (const float*)d_in[0];
    const int*   y = (const int*)d_in[1];
    float* out = (float*)d_out;

    cudaFuncSetAttribute(scl_mma_kernel,
                         cudaFuncAttributeMaxDynamicSharedMemorySize, SMEM_TOTAL);

    norm_kernel<<<NROW / 16, 256>>>(x);
    scl_mma_kernel<<<GRID, THREADS, SMEM_TOTAL>>>(y);
    finish_kernel<<<64, 128>>>(out);
}

// round 16
// speedup vs baseline: 1.3014x; 1.2703x over previous
#include <cuda_runtime.h>
#include <cuda_bf16.h>
#include <stdint.h>
#include <math.h>

#define NROW 8192
#define THREADS 512
#define GRID 148
#define STRIDE_B 272u            // 136 bf16 per smem row (17x16B, conflict-free)
#define TILEB (128u * STRIDE_B)  // 34816
#define BUFOFF(b) ((uint32_t)(b) * 2u * TILEB)   // A at +0, B at +TILEB
#define YOFF   (4u * TILEB)                       // 139264: 2 bufs x 1024B
#define IP_OFF (YOFF + 2048u)                     // 141312: 3 x 10240B (128 rows x 20 words)
#define JP_OFF (IP_OFF + 30720u)                  // 172032: 3 x 18432B (128 cols x 36 words)
#define SMEM_TOTAL (JP_OFF + 55296u)              // 227328 <= 232448

#define PLANE 524288             // 64*64*128 floats per stat plane

__device__ __nv_bfloat16 g_xb[NROW * 128];
// P[s][a][b][r]: s=0 denom, 1 S, 2 m. Every slot written exactly once per launch.
__device__ float g_P[3 * PLANE];
__device__ float g_part[64];
__device__ int   g_ctr;          // zero-init; self-resets each launch

// ---------------- PTX helpers ----------------
__device__ __forceinline__ uint32_t smem_u32(const void* p) {
    uint32_t a;
    asm("{ .reg .u64 t; cvta.to.shared.u64 t, %1; cvt.u32.u64 %0, t; }" : "=r"(a) : "l"(p));
    return a;
}
#define LDSM4(r, a) \
    asm volatile("ldmatrix.sync.aligned.m8n8.x4.shared.b16 {%0,%1,%2,%3}, [%4];" \
        : "=r"((r)[0]), "=r"((r)[1]), "=r"((r)[2]), "=r"((r)[3]) : "r"(a))
#define MMA16816(c, a, b0v, b1v) \
    asm volatile("mma.sync.aligned.m16n8k16.row.col.f32.bf16.bf16.f32 " \
        "{%0,%1,%2,%3}, {%4,%5,%6,%7}, {%8,%9}, {%0,%1,%2,%3};" \
        : "+f"((c)[0]), "+f"((c)[1]), "+f"((c)[2]), "+f"((c)[3]) \
        : "r"((a)[0]), "r"((a)[1]), "r"((a)[2]), "r"((a)[3]), "r"(b0v), "r"(b1v))
#define CP_ASYNC16(dst, src) \
    asm volatile("cp.async.cg.shared.global [%0], [%1], 16;" :: "r"(dst), "l"(src))
#define CP_ASYNC4(dst, src) \
    asm volatile("cp.async.ca.shared.global [%0], [%1], 4;" :: "r"(dst), "l"(src))
#define CP_COMMIT() asm volatile("cp.async.commit_group;" ::: "memory")
#define CP_WAIT1()  asm volatile("cp.async.wait_group 1;" ::: "memory")
#define CP_WAIT0()  asm volatile("cp.async.wait_group 0;" ::: "memory")

// ---------------- Kernel 1: normalize + bf16 convert (8 rows/warp, MLP=8) --------
__global__ void __launch_bounds__(256) norm_kernel(const float* __restrict__ x) {
    int warp = threadIdx.x >> 5, lane = threadIdx.x & 31;
    int row0 = (blockIdx.x * 8 + warp) * 8;
    float4 v[8];
#pragma unroll
    for (int r = 0; r < 8; ++r)
        v[r] = reinterpret_cast<const float4*>(x)[(row0 + r) * 32 + lane];
    float ss[8];
#pragma unroll
    for (int r = 0; r < 8; ++r)
        ss[r] = v[r].x * v[r].x + v[r].y * v[r].y + v[r].z * v[r].z + v[r].w * v[r].w;
#pragma unroll
    for (int o = 16; o; o >>= 1)
#pragma unroll
        for (int r = 0; r < 8; ++r)
            ss[r] += __shfl_xor_sync(0xffffffffu, ss[r], o);
#pragma unroll
    for (int r = 0; r < 8; ++r) {
        float inv = 1.0f / fmaxf(sqrtf(ss[r]), 1e-12f);
        float4 w = v[r];
        w.x *= inv; w.y *= inv; w.z *= inv; w.w *= inv;
        uint32_t p0 = ((uint32_t)__bfloat16_as_ushort(__float2bfloat16(w.y)) << 16)
                    |  (uint32_t)__bfloat16_as_ushort(__float2bfloat16(w.x));
        uint32_t p1 = ((uint32_t)__bfloat16_as_ushort(__float2bfloat16(w.w)) << 16)
                    |  (uint32_t)__bfloat16_as_ushort(__float2bfloat16(w.z));
        reinterpret_cast<uint2*>(g_xb)[(row0 + r) * 32 + lane] = make_uint2(p0, p1);
    }
}

// ---------------- off-diagonal index u in [0,2016) -> (bi, bj), bi < bj ----------------
__device__ __forceinline__ void offdiag(int u, int& bi, int& bj) {
    int k = (int)((1.0f + __fsqrt_rn(1.0f + 8.0f * (float)u)) * 0.5f);
    while (k * (k - 1) / 2 > u) --k;
    while ((k + 1) * k / 2 <= u) ++k;
    bi = 63 - k;
    bj = 63 - (u - k * (k - 1) / 2);
}

// Balanced schedule: CTAs 0-7 run 15 tiles (8 diagonal + 7 off-diag);
// CTAs 8-147 run 14 off-diag tiles.
__device__ __forceinline__ void sched(int b, int it, int& bi, int& bj) {
    if (b < 8) {
        if (it < 8) { bi = bj = b * 8 + it; return; }
        offdiag(b * 7 + (it - 8), bi, bj);
    } else {
        offdiag(56 + (b - 8) * 14 + it, bi, bj);
    }
}

__device__ __forceinline__ void prefetch_tile(uint32_t sbase, int buf,
                                              int bi, int bj, const uint4* xg,
                                              const int* y, int tid) {
    uint32_t dst = sbase + BUFOFF(buf);
    const int arow = bi * 128, brow = bj * 128;
#pragma unroll
    for (int q = 0; q < 4; ++q) {
        int idx = tid + q * THREADS;
        int row = idx >> 4, c16 = idx & 15;
        CP_ASYNC16(dst + row * STRIDE_B + c16 * 16, (const void*)(xg + (arow + row) * 16 + c16));
    }
#pragma unroll
    for (int q = 0; q < 4; ++q) {
        int idx = tid + q * THREADS;
        int row = idx >> 4, c16 = idx & 15;
        CP_ASYNC16(dst + TILEB + row * STRIDE_B + c16 * 16, (const void*)(xg + (brow + row) * 16 + c16));
    }
    if (tid < 128)
        CP_ASYNC4(sbase + YOFF + (uint32_t)buf * 1024u + tid * 4, (const void*)(y + arow + tid));
    else if (tid < 256)
        CP_ASYNC4(sbase + YOFF + (uint32_t)buf * 1024u + 512u + (tid - 128) * 4,
                  (const void*)(y + brow + (tid - 128)));
    CP_COMMIT();
}

// ---------------- Kernel 2: symmetric Gram + dual-orientation stats ----------------
__global__ void __launch_bounds__(THREADS, 1) scl_mma_kernel(const int* __restrict__ y) {
    extern __shared__ char smem[];
    const uint32_t sbase = smem_u32(smem);
    const int tid = threadIdx.x, wid = tid >> 5, lane = tid & 31;
    const int wi = wid & 3, wj = wid >> 2;
    const int grp = lane >> 2;
    const int b = blockIdx.x;
    const int niter = (b < 8) ? 15 : 14;

    const uint4* xg = reinterpret_cast<const uint4*>(g_xb);
    float* ipE = reinterpret_cast<float*>(smem + IP_OFF);          // 128 x 20 words
    float* ipS = ipE + 2560; float* ipM = ipE + 5120;
    float* jpE = reinterpret_cast<float*>(smem + JP_OFF);          // 128 x 36 words
    float* jpS = jpE + 4608; float* jpM = jpE + 9216;

    // relative ldmatrix offsets (buffer base added per tile)
    uint32_t aRel[2], bRel[2];
#pragma unroll
    for (int mi = 0; mi < 2; ++mi)
        aRel[mi] = (uint32_t)((wi * 32 + mi * 16 + (lane & 15)) * STRIDE_B + (lane >> 4) * 16);
#pragma unroll
    for (int nb = 0; nb < 2; ++nb)
        bRel[nb] = (uint32_t)((wj * 32 + nb * 16 + (lane & 7) + (lane >> 4) * 8) * STRIDE_B
                   + ((lane >> 3) & 1) * 16);

    {
        int bi0, bj0; sched(b, 0, bi0, bj0);
        prefetch_tile(sbase, 0, bi0, bj0, xg, y, tid);
    }

    for (int it = 0; it < niter; ++it) {
        int bi, bj; sched(b, it, bi, bj);
        if (it + 1 < niter) {
            int nbi, nbj; sched(b, it + 1, nbi, nbj);
            prefetch_tile(sbase, (it + 1) & 1, nbi, nbj, xg, y, tid);
            CP_WAIT1();
        } else {
            CP_WAIT0();
        }
        __syncthreads();

        const uint32_t abase = sbase + BUFOFF(it & 1);
        const uint32_t bbase = abase + TILEB;
        const int* yI = reinterpret_cast<const int*>(smem + YOFF + (it & 1) * 1024);
        const int* yJ = yI + 128;
        const bool isDiag = (bi == bj);

        float acc[2][4][4];
#pragma unroll
        for (int mi = 0; mi < 2; ++mi)
#pragma unroll
            for (int p = 0; p < 4; ++p)
#pragma unroll
                for (int c = 0; c < 4; ++c) acc[mi][p][c] = 0.f;

        // Software-pipelined k-loop: LDSM(kk+1) issued BEFORE MMAs(kk), so each
        // MMA's operands were loaded a full iteration earlier (volatile keeps order).
        {
            uint32_t a0[2][4], a1[2][4], b0[2][4], b1[2][4];
            LDSM4(a0[0], abase + aRel[0]);
            LDSM4(a1[0], abase + aRel[1]);
            LDSM4(b0[0], bbase + bRel[0]);
            LDSM4(b1[0], bbase + bRel[1]);
#pragma unroll
            for (int kk = 0; kk < 8; ++kk) {
                const int cur = kk & 1, nxt = cur ^ 1;
                if (kk < 7) {
                    LDSM4(a0[nxt], abase + aRel[0] + (kk + 1) * 32);
                    LDSM4(a1[nxt], abase + aRel[1] + (kk + 1) * 32);
                    LDSM4(b0[nxt], bbase + bRel[0] + (kk + 1) * 32);
                    LDSM4(b1[nxt], bbase + bRel[1] + (kk + 1) * 32);
                }
                MMA16816(acc[0][0], a0[cur], b0[cur][0], b0[cur][1]);
                MMA16816(acc[0][1], a0[cur], b0[cur][2], b0[cur][3]);
                MMA16816(acc[0][2], a0[cur], b1[cur][0], b1[cur][1]);
                MMA16816(acc[0][3], a0[cur], b1[cur][2], b1[cur][3]);
                MMA16816(acc[1][0], a1[cur], b0[cur][0], b0[cur][1]);
                MMA16816(acc[1][1], a1[cur], b0[cur][2], b0[cur][3]);
                MMA16816(acc[1][2], a1[cur], b1[cur][0], b1[cur][1]);
                MMA16816(acc[1][3], a1[cur], b1[cur][2], b1[cur][3]);
            }
        }

        int yiv[2][2];
#pragma unroll
        for (int mi = 0; mi < 2; ++mi)
#pragma unroll
            for (int rh = 0; rh < 2; ++rh)
                yiv[mi][rh] = yI[wi * 32 + mi * 16 + rh * 8 + grp];

        float dnm[2][2] = {{0.f,0.f},{0.f,0.f}};
        float Ss [2][2] = {{0.f,0.f},{0.f,0.f}};
        float mm [2][2] = {{0.f,0.f},{0.f,0.f}};

        if (!isDiag) {
#pragma unroll
            for (int p = 0; p < 4; ++p) {
                const int jl = wj * 32 + (p >> 1) * 16 + (p & 1) * 8 + 2 * (lane & 3);
                const int yj0 = yJ[jl], yj1 = yJ[jl + 1];
                float cE0=0.f,cE1=0.f,cS0=0.f,cS1=0.f,cM0=0.f,cM1=0.f;
#pragma unroll
                for (int mi = 0; mi < 2; ++mi)
#pragma unroll
                    for (int rh = 0; rh < 2; ++rh) {
                        const float d0 = acc[mi][p][rh * 2 + 0];
                        const float d1 = acc[mi][p][rh * 2 + 1];
                        const float e0 = __expf(10.0f * d0);
                        const float e1 = __expf(10.0f * d1);
                        const int yi = yiv[mi][rh];
                        const float m0 = (yj0 == yi) ? 1.0f : 0.0f;
                        const float m1 = (yj1 == yi) ? 1.0f : 0.0f;
                        dnm[mi][rh] += e0 + e1;
                        Ss[mi][rh]  = fmaf(d0, m0, fmaf(d1, m1, Ss[mi][rh]));
                        mm[mi][rh] += m0 + m1;
                        cE0 += e0; cE1 += e1;
                        cS0 = fmaf(d0, m0, cS0); cS1 = fmaf(d1, m1, cS1);
                        cM0 += m0; cM1 += m1;
                    }
                const int s0 = jl * 36 + wi * 8 + grp, s1 = s0 + 36;
                jpE[s0] = cE0; jpE[s1] = cE1;
                jpS[s0] = cS0; jpS[s1] = cS1;
                jpM[s0] = cM0; jpM[s1] = cM1;
            }
        } else {
#pragma unroll
            for (int p = 0; p < 4; ++p) {
                const int jl = wj * 32 + (p >> 1) * 16 + (p & 1) * 8 + 2 * (lane & 3);
                const int yj0 = yJ[jl], yj1 = yJ[jl + 1];
#pragma unroll
                for (int mi = 0; mi < 2; ++mi)
#pragma unroll
                    for (int rh = 0; rh < 2; ++rh) {
                        const float d0 = acc[mi][p][rh * 2 + 0];
                        const float d1 = acc[mi][p][rh * 2 + 1];
                        float e0 = __expf(10.0f * d0);
                        float e1 = __expf(10.0f * d1);
                        const int yi = yiv[mi][rh];
                        const int rowloc = wi * 32 + mi * 16 + rh * 8 + grp;
                        float m0 = (yj0 == yi) ? 1.0f : 0.0f;
                        float m1 = (yj1 == yi) ? 1.0f : 0.0f;
                        if (jl == rowloc)     { e0 = 0.0f; m0 = 0.0f; }
                        if (jl + 1 == rowloc) { e1 = 0.0f; m1 = 0.0f; }
                        dnm[mi][rh] += e0 + e1;
                        Ss[mi][rh]  = fmaf(d0, m0, fmaf(d1, m1, Ss[mi][rh]));
                        mm[mi][rh] += m0 + m1;
                    }
            }
        }

        // i-orientation per-thread partials: row slot = row*20 + wj*4 + (lane&3)
#pragma unroll
        for (int mi = 0; mi < 2; ++mi)
#pragma unroll
            for (int rh = 0; rh < 2; ++rh) {
                const int row = wi * 32 + mi * 16 + rh * 8 + grp;
                const int sl = row * 20 + wj * 4 + (lane & 3);
                ipE[sl] = dnm[mi][rh]; ipS[sl] = Ss[mi][rh]; ipM[sl] = mm[mi][rh];
            }
        __syncthreads();

        // store phase: sum partials, write g_P (each slot exactly once per launch)
        const int ntask = isDiag ? 384 : 768;
        for (int task = tid; task < ntask; task += THREADS) {
            if (task < 384) {
                const int stat = task >> 7, row = task & 127;
                const float* src = ipE + stat * 2560 + row * 20;
                float s = 0.f;
#pragma unroll
                for (int q = 0; q < 4; ++q) {
                    float4 v = *reinterpret_cast<const float4*>(src + q * 4);
                    s += (v.x + v.y) + (v.z + v.w);
                }
                g_P[stat * PLANE + bi * 8192 + bj * 128 + row] = s;
            } else {
                const int tt = task - 384;
                const int stat = tt >> 7, col = tt & 127;
                const float* src = jpE + stat * 4608 + col * 36;
                float s = 0.f;
#pragma unroll
                for (int q = 0; q < 8; ++q) {
                    float4 v = *reinterpret_cast<const float4*>(src + q * 4);
                    s += (v.x + v.y) + (v.z + v.w);
                }
                g_P[stat * PLANE + bj * 8192 + bi * 128 + col] = s;
            }
        }
        // loop-top CP_WAIT + __syncthreads orders partial-zone reuse next iteration
    }
}

// ---------------- Kernel 3: fused per-row loss + global sum ----------------
__global__ void __launch_bounds__(128) finish_kernel(float* __restrict__ out) {
    const int A = blockIdx.x, r = threadIdx.x;
    float D = 0.f, S = 0.f, M = 0.f;
    const int base = A * 8192 + r;
#pragma unroll 8
    for (int c = 0; c < 64; ++c) {
        D += g_P[base + c * 128];
        S += g_P[PLANE + base + c * 128];
        M += g_P[2 * PLANE + base + c * 128];
    }
    float v = (M > 0.5f) ? (logf(D) - 10.0f * S / M) : 0.0f;
    __shared__ float red[4];
#pragma unroll
    for (int o = 16; o; o >>= 1) v += __shfl_xor_sync(0xffffffffu, v, o);
    if ((r & 31) == 0) red[r >> 5] = v;
    __syncthreads();
    if (r == 0) {
        g_part[A] = (red[0] + red[1]) + (red[2] + red[3]);
        __threadfence();
        if (atomicAdd(&g_ctr, 1) == 63) {
            float s = 0.f;
#pragma unroll 8
            for (int i = 0; i < 64; ++i) s += g_part[i];
            out[0] = s;
            g_ctr = 0;     // reset for graph replay
        }
    }
}

// ---------------------------------------------------------------------------
extern "C" void kernel_launch(void* const* d_in, const int* in_sizes, int n_in,
                              void* d_out, int out_size) {
    (void)in_sizes; (void)n_in; (void)out_size;
    const float* x = (const float*)d_in[0];
    const int*   y = (const int*)d_in[1];
    float* out = (float*)d_out;

    cudaFuncSetAttribute(scl_mma_kernel,
                         cudaFuncAttributeMaxDynamicSharedMemorySize, SMEM_TOTAL);

    norm_kernel<<<NROW / 64, 256>>>(x);
    scl_mma_kernel<<<GRID, THREADS, SMEM_TOTAL>>>(y);
    finish_kernel<<<64, 128>>>(out);
}

// round 17
// speedup vs baseline: 1.3896x; 1.0678x over previous
#include <cuda_runtime.h>
#include <cuda_bf16.h>
#include <stdint.h>
#include <math.h>

#define NROW 8192
#define THREADS 512
#define GRID 148
#define STRIDE_B 272u            // 136 bf16 per smem row (17x16B, conflict-free)
#define TILEB (128u * STRIDE_B)  // 34816
#define BUFOFF(b) ((uint32_t)(b) * 2u * TILEB)   // A at +0, B at +TILEB
#define YOFF   (4u * TILEB)                       // 139264: 2 bufs x 1024B
#define IP_OFF (YOFF + 2048u)                     // 141312: 3 x 10240B (128 rows x 20 words)
#define JP_OFF (IP_OFF + 30720u)                  // 172032: 3 x 18432B (128 cols x 36 words)
#define SMEM_TOTAL (JP_OFF + 55296u)              // 227328 <= 232448

#define PLANE 524288             // 64*64*128 floats per stat plane
#define QSCALE 3.7982826f        // sqrt(10/ln2): acc gives d' = (10/ln2) * dot
#define LN2 0.69314718f

__device__ __nv_bfloat16 g_xb[NROW * 128];
// P[s][a][b][r]: s=0 denom, 1 S', 2 m. Every slot written exactly once per launch.
__device__ float g_P[3 * PLANE];
__device__ float g_part[64];
__device__ int   g_ctr;          // zero-init; self-resets each launch

// ---------------- PTX helpers ----------------
__device__ __forceinline__ uint32_t smem_u32(const void* p) {
    uint32_t a;
    asm("{ .reg .u64 t; cvta.to.shared.u64 t, %1; cvt.u32.u64 %0, t; }" : "=r"(a) : "l"(p));
    return a;
}
#define LDSM4(r, a) \
    asm volatile("ldmatrix.sync.aligned.m8n8.x4.shared.b16 {%0,%1,%2,%3}, [%4];" \
        : "=r"((r)[0]), "=r"((r)[1]), "=r"((r)[2]), "=r"((r)[3]) : "r"(a))
#define MMA16816(c, a, b0v, b1v) \
    asm volatile("mma.sync.aligned.m16n8k16.row.col.f32.bf16.bf16.f32 " \
        "{%0,%1,%2,%3}, {%4,%5,%6,%7}, {%8,%9}, {%0,%1,%2,%3};" \
        : "+f"((c)[0]), "+f"((c)[1]), "+f"((c)[2]), "+f"((c)[3]) \
        : "r"((a)[0]), "r"((a)[1]), "r"((a)[2]), "r"((a)[3]), "r"(b0v), "r"(b1v))
#define CP_ASYNC16(dst, src) \
    asm volatile("cp.async.cg.shared.global [%0], [%1], 16;" :: "r"(dst), "l"(src))
#define CP_ASYNC4(dst, src) \
    asm volatile("cp.async.ca.shared.global [%0], [%1], 4;" :: "r"(dst), "l"(src))
#define CP_COMMIT() asm volatile("cp.async.commit_group;" ::: "memory")
#define CP_WAIT1()  asm volatile("cp.async.wait_group 1;" ::: "memory")
#define CP_WAIT0()  asm volatile("cp.async.wait_group 0;" ::: "memory")
// packed f32x2 (sm_100+ base ISA; ptxas won't auto-fuse, explicit PTX required)
#define EX2(e, d)       asm("ex2.approx.ftz.f32 %0, %1;" : "=f"(e) : "f"(d))
#define PACK2(o, lo, hi) asm("mov.b64 %0, {%1, %2};" : "=l"(o) : "f"(lo), "f"(hi))
#define UNPK2(lo, hi, i) asm("mov.b64 {%0, %1}, %2;" : "=f"(lo), "=f"(hi) : "l"(i))
#define ADDX2(o, a, b)  asm("add.rn.f32x2 %0, %1, %2;" : "=l"(o) : "l"(a), "l"(b))
#define FMAX2(o, a, b, c) asm("fma.rn.f32x2 %0, %1, %2, %3;" : "=l"(o) : "l"(a), "l"(b), "l"(c))

// ---------------- Kernel 1: normalize + prescale + bf16 convert (2 rows/warp) ----
__global__ void __launch_bounds__(256) norm_kernel(const float* __restrict__ x) {
    int warp = threadIdx.x >> 5, lane = threadIdx.x & 31;
    int row0 = (blockIdx.x * 8 + warp) * 2;
    float4 v0 = reinterpret_cast<const float4*>(x)[row0 * 32 + lane];
    float4 v1 = reinterpret_cast<const float4*>(x)[(row0 + 1) * 32 + lane];
    float s0 = v0.x * v0.x + v0.y * v0.y + v0.z * v0.z + v0.w * v0.w;
    float s1 = v1.x * v1.x + v1.y * v1.y + v1.z * v1.z + v1.w * v1.w;
#pragma unroll
    for (int o = 16; o; o >>= 1) {
        s0 += __shfl_xor_sync(0xffffffffu, s0, o);
        s1 += __shfl_xor_sync(0xffffffffu, s1, o);
    }
    float i0 = QSCALE / fmaxf(sqrtf(s0), 1e-12f);
    float i1 = QSCALE / fmaxf(sqrtf(s1), 1e-12f);
    v0.x *= i0; v0.y *= i0; v0.z *= i0; v0.w *= i0;
    v1.x *= i1; v1.y *= i1; v1.z *= i1; v1.w *= i1;
    uint32_t a0 = ((uint32_t)__bfloat16_as_ushort(__float2bfloat16(v0.y)) << 16)
                |  (uint32_t)__bfloat16_as_ushort(__float2bfloat16(v0.x));
    uint32_t a1 = ((uint32_t)__bfloat16_as_ushort(__float2bfloat16(v0.w)) << 16)
                |  (uint32_t)__bfloat16_as_ushort(__float2bfloat16(v0.z));
    uint32_t b0 = ((uint32_t)__bfloat16_as_ushort(__float2bfloat16(v1.y)) << 16)
                |  (uint32_t)__bfloat16_as_ushort(__float2bfloat16(v1.x));
    uint32_t b1 = ((uint32_t)__bfloat16_as_ushort(__float2bfloat16(v1.w)) << 16)
                |  (uint32_t)__bfloat16_as_ushort(__float2bfloat16(v1.z));
    reinterpret_cast<uint2*>(g_xb)[row0 * 32 + lane] = make_uint2(a0, a1);
    reinterpret_cast<uint2*>(g_xb)[(row0 + 1) * 32 + lane] = make_uint2(b0, b1);
}

// ---------------- off-diagonal index u in [0,2016) -> (bi, bj), bi < bj ----------------
__device__ __forceinline__ void offdiag(int u, int& bi, int& bj) {
    int k = (int)((1.0f + __fsqrt_rn(1.0f + 8.0f * (float)u)) * 0.5f);
    while (k * (k - 1) / 2 > u) --k;
    while ((k + 1) * k / 2 <= u) ++k;
    bi = 63 - k;
    bj = 63 - (u - k * (k - 1) / 2);
}

// Balanced schedule: CTAs 0-7 run 15 tiles (8 diagonal + 7 off-diag);
// CTAs 8-147 run 14 off-diag tiles.
__device__ __forceinline__ void sched(int b, int it, int& bi, int& bj) {
    if (b < 8) {
        if (it < 8) { bi = bj = b * 8 + it; return; }
        offdiag(b * 7 + (it - 8), bi, bj);
    } else {
        offdiag(56 + (b - 8) * 14 + it, bi, bj);
    }
}

__device__ __forceinline__ void prefetch_tile(uint32_t sbase, int buf,
                                              int bi, int bj, const uint4* xg,
                                              const int* y, int tid) {
    uint32_t dst = sbase + BUFOFF(buf);
    const int arow = bi * 128, brow = bj * 128;
#pragma unroll
    for (int q = 0; q < 4; ++q) {
        int idx = tid + q * THREADS;
        int row = idx >> 4, c16 = idx & 15;
        CP_ASYNC16(dst + row * STRIDE_B + c16 * 16, (const void*)(xg + (arow + row) * 16 + c16));
    }
#pragma unroll
    for (int q = 0; q < 4; ++q) {
        int idx = tid + q * THREADS;
        int row = idx >> 4, c16 = idx & 15;
        CP_ASYNC16(dst + TILEB + row * STRIDE_B + c16 * 16, (const void*)(xg + (brow + row) * 16 + c16));
    }
    if (tid < 128)
        CP_ASYNC4(sbase + YOFF + (uint32_t)buf * 1024u + tid * 4, (const void*)(y + arow + tid));
    else if (tid < 256)
        CP_ASYNC4(sbase + YOFF + (uint32_t)buf * 1024u + 512u + (tid - 128) * 4,
                  (const void*)(y + brow + (tid - 128)));
    CP_COMMIT();
}

// ---------------- Kernel 2: symmetric Gram + packed-f32x2 epilogue ----------------
__global__ void __launch_bounds__(THREADS, 1) scl_mma_kernel(const int* __restrict__ y) {
    extern __shared__ char smem[];
    const uint32_t sbase = smem_u32(smem);
    const int tid = threadIdx.x, wid = tid >> 5, lane = tid & 31;
    const int wi = wid & 3, wj = wid >> 2;
    const int grp = lane >> 2;
    const int b = blockIdx.x;
    const int niter = (b < 8) ? 15 : 14;

    const uint4* xg = reinterpret_cast<const uint4*>(g_xb);
    float* ipE = reinterpret_cast<float*>(smem + IP_OFF);          // 128 x 20 words
    float* ipS = ipE + 2560; float* ipM = ipE + 5120;
    float* jpE = reinterpret_cast<float*>(smem + JP_OFF);          // 128 x 36 words
    float* jpS = jpE + 4608; float* jpM = jpE + 9216;

    uint32_t aRel[2], bRel[2];
#pragma unroll
    for (int mi = 0; mi < 2; ++mi)
        aRel[mi] = (uint32_t)((wi * 32 + mi * 16 + (lane & 15)) * STRIDE_B + (lane >> 4) * 16);
#pragma unroll
    for (int nb = 0; nb < 2; ++nb)
        bRel[nb] = (uint32_t)((wj * 32 + nb * 16 + (lane & 7) + (lane >> 4) * 8) * STRIDE_B
                   + ((lane >> 3) & 1) * 16);

    {
        int bi0, bj0; sched(b, 0, bi0, bj0);
        prefetch_tile(sbase, 0, bi0, bj0, xg, y, tid);
    }

    for (int it = 0; it < niter; ++it) {
        int bi, bj; sched(b, it, bi, bj);
        if (it + 1 < niter) {
            int nbi, nbj; sched(b, it + 1, nbi, nbj);
            prefetch_tile(sbase, (it + 1) & 1, nbi, nbj, xg, y, tid);
            CP_WAIT1();
        } else {
            CP_WAIT0();
        }
        __syncthreads();

        const uint32_t abase = sbase + BUFOFF(it & 1);
        const uint32_t bbase = abase + TILEB;
        const int* yI = reinterpret_cast<const int*>(smem + YOFF + (it & 1) * 1024);
        const int* yJ = yI + 128;
        const bool isDiag = (bi == bj);

        float acc[2][4][4];
#pragma unroll
        for (int mi = 0; mi < 2; ++mi)
#pragma unroll
            for (int p = 0; p < 4; ++p)
#pragma unroll
                for (int c = 0; c < 4; ++c) acc[mi][p][c] = 0.f;

#pragma unroll
        for (int kk = 0; kk < 8; ++kk) {
            uint32_t a0[4], a1[4], b0[4], b1[4];
            LDSM4(a0, abase + aRel[0] + kk * 32);
            LDSM4(a1, abase + aRel[1] + kk * 32);
            LDSM4(b0, bbase + bRel[0] + kk * 32);
            LDSM4(b1, bbase + bRel[1] + kk * 32);
            MMA16816(acc[0][0], a0, b0[0], b0[1]);
            MMA16816(acc[0][1], a0, b0[2], b0[3]);
            MMA16816(acc[0][2], a0, b1[0], b1[1]);
            MMA16816(acc[0][3], a0, b1[2], b1[3]);
            MMA16816(acc[1][0], a1, b0[0], b0[1]);
            MMA16816(acc[1][1], a1, b0[2], b0[3]);
            MMA16816(acc[1][2], a1, b1[0], b1[1]);
            MMA16816(acc[1][3], a1, b1[2], b1[3]);
        }

        int yiv[2][2];
#pragma unroll
        for (int mi = 0; mi < 2; ++mi)
#pragma unroll
            for (int rh = 0; rh < 2; ++rh)
                yiv[mi][rh] = yI[wi * 32 + mi * 16 + rh * 8 + grp];

        // packed i-orientation accumulators: (col0, col1) lanes summed at store
        uint64_t dnmP[2][2], SsP[2][2], mmP[2][2];
#pragma unroll
        for (int mi = 0; mi < 2; ++mi)
#pragma unroll
            for (int rh = 0; rh < 2; ++rh) { dnmP[mi][rh] = 0ull; SsP[mi][rh] = 0ull; mmP[mi][rh] = 0ull; }

        if (!isDiag) {
#pragma unroll
            for (int p = 0; p < 4; ++p) {
                const int jl = wj * 32 + (p >> 1) * 16 + (p & 1) * 8 + 2 * (lane & 3);
                const int yj0 = yJ[jl], yj1 = yJ[jl + 1];
                uint64_t cE = 0ull, cS = 0ull, cM = 0ull;
#pragma unroll
                for (int mi = 0; mi < 2; ++mi)
#pragma unroll
                    for (int rh = 0; rh < 2; ++rh) {
                        const float d0 = acc[mi][p][rh * 2 + 0];
                        const float d1 = acc[mi][p][rh * 2 + 1];
                        float e0, e1; EX2(e0, d0); EX2(e1, d1);
                        const int yi = yiv[mi][rh];
                        const float m0 = (yj0 == yi) ? 1.0f : 0.0f;
                        const float m1 = (yj1 == yi) ? 1.0f : 0.0f;
                        uint64_t E, D, Mk;
                        PACK2(E, e0, e1); PACK2(D, d0, d1); PACK2(Mk, m0, m1);
                        ADDX2(dnmP[mi][rh], dnmP[mi][rh], E);
                        FMAX2(SsP[mi][rh], D, Mk, SsP[mi][rh]);
                        ADDX2(mmP[mi][rh], mmP[mi][rh], Mk);
                        ADDX2(cE, cE, E);
                        FMAX2(cS, D, Mk, cS);
                        ADDX2(cM, cM, Mk);
                    }
                float cE0, cE1, cS0, cS1, cM0, cM1;
                UNPK2(cE0, cE1, cE); UNPK2(cS0, cS1, cS); UNPK2(cM0, cM1, cM);
                const int s0 = jl * 36 + wi * 8 + grp, s1 = s0 + 36;
                jpE[s0] = cE0; jpE[s1] = cE1;
                jpS[s0] = cS0; jpS[s1] = cS1;
                jpM[s0] = cM0; jpM[s1] = cM1;
            }
        } else {
#pragma unroll
            for (int p = 0; p < 4; ++p) {
                const int jl = wj * 32 + (p >> 1) * 16 + (p & 1) * 8 + 2 * (lane & 3);
                const int yj0 = yJ[jl], yj1 = yJ[jl + 1];
#pragma unroll
                for (int mi = 0; mi < 2; ++mi)
#pragma unroll
                    for (int rh = 0; rh < 2; ++rh) {
                        const float d0 = acc[mi][p][rh * 2 + 0];
                        const float d1 = acc[mi][p][rh * 2 + 1];
                        float e0, e1; EX2(e0, d0); EX2(e1, d1);
                        const int yi = yiv[mi][rh];
                        const int rowloc = wi * 32 + mi * 16 + rh * 8 + grp;
                        float m0 = (yj0 == yi) ? 1.0f : 0.0f;
                        float m1 = (yj1 == yi) ? 1.0f : 0.0f;
                        if (jl == rowloc)     { e0 = 0.0f; m0 = 0.0f; }
                        if (jl + 1 == rowloc) { e1 = 0.0f; m1 = 0.0f; }
                        uint64_t E, D, Mk;
                        PACK2(E, e0, e1); PACK2(D, d0, d1); PACK2(Mk, m0, m1);
                        ADDX2(dnmP[mi][rh], dnmP[mi][rh], E);
                        FMAX2(SsP[mi][rh], D, Mk, SsP[mi][rh]);
                        ADDX2(mmP[mi][rh], mmP[mi][rh], Mk);
                    }
            }
        }

        // i-orientation partials: unpack packed accumulators (lo+hi) and store
#pragma unroll
        for (int mi = 0; mi < 2; ++mi)
#pragma unroll
            for (int rh = 0; rh < 2; ++rh) {
                const int row = wi * 32 + mi * 16 + rh * 8 + grp;
                const int sl = row * 20 + wj * 4 + (lane & 3);
                float lo, hi;
                UNPK2(lo, hi, dnmP[mi][rh]); ipE[sl] = lo + hi;
                UNPK2(lo, hi, SsP[mi][rh]);  ipS[sl] = lo + hi;
                UNPK2(lo, hi, mmP[mi][rh]);  ipM[sl] = lo + hi;
            }
        __syncthreads();

        // store phase: sum partials, write g_P (each slot exactly once per launch)
        const int ntask = isDiag ? 384 : 768;
        for (int task = tid; task < ntask; task += THREADS) {
            if (task < 384) {
                const int stat = task >> 7, row = task & 127;
                const float* src = ipE + stat * 2560 + row * 20;
                float s = 0.f;
#pragma unroll
                for (int q = 0; q < 4; ++q) {
                    float4 v = *reinterpret_cast<const float4*>(src + q * 4);
                    s += (v.x + v.y) + (v.z + v.w);
                }
                g_P[stat * PLANE + bi * 8192 + bj * 128 + row] = s;
            } else {
                const int tt = task - 384;
                const int stat = tt >> 7, col = tt & 127;
                const float* src = jpE + stat * 4608 + col * 36;
                float s = 0.f;
#pragma unroll
                for (int q = 0; q < 8; ++q) {
                    float4 v = *reinterpret_cast<const float4*>(src + q * 4);
                    s += (v.x + v.y) + (v.z + v.w);
                }
                g_P[stat * PLANE + bj * 8192 + bi * 128 + col] = s;
            }
        }
        // loop-top CP_WAIT + __syncthreads orders partial-zone reuse next iteration
    }
}

// ---------------- Kernel 3: fused per-row loss + global sum ----------------
__global__ void __launch_bounds__(128) finish_kernel(float* __restrict__ out) {
    const int A = blockIdx.x, r = threadIdx.x;
    float D = 0.f, S = 0.f, M = 0.f;
    const int base = A * 8192 + r;
#pragma unroll 8
    for (int c = 0; c < 64; ++c) {
        D += g_P[base + c * 128];
        S += g_P[PLANE + base + c * 128];
        M += g_P[2 * PLANE + base + c * 128];
    }
    // S is in d' units (d' = (10/ln2) d): 10*S_orig/m == ln2*S/m
    float v = (M > 0.5f) ? (logf(D) - LN2 * S / M) : 0.0f;
    __shared__ float red[4];
#pragma unroll
    for (int o = 16; o; o >>= 1) v += __shfl_xor_sync(0xffffffffu, v, o);
    if ((r & 31) == 0) red[r >> 5] = v;
    __syncthreads();
    if (r == 0) {
        g_part[A] = (red[0] + red[1]) + (red[2] + red[3]);
        __threadfence();
        if (atomicAdd(&g_ctr, 1) == 63) {
            float s = 0.f;
#pragma unroll 8
            for (int i = 0; i < 64; ++i) s += g_part[i];
            out[0] = s;
            g_ctr = 0;     // reset for graph replay
        }
    }
}

// ---------------------------------------------------------------------------
extern "C" void kernel_launch(void* const* d_in, const int* in_sizes, int n_in,
                              void* d_out, int out_size) {
    (void)in_sizes; (void)n_in; (void)out_size;
    const float* x = (const float*)d_in[0];
    const int*   y = (const int*)d_in[1];
    float* out = (float*)d_out;

    cudaFuncSetAttribute(scl_mma_kernel,
                         cudaFuncAttributeMaxDynamicSharedMemorySize, SMEM_TOTAL);

    norm_kernel<<<NROW / 16, 256>>>(x);
    scl_mma_kernel<<<GRID, THREADS, SMEM_TOTAL>>>(y);
    finish_kernel<<<64, 128>>>(out);
}